// round 13
// baseline (speedup 1.0000x reference)
#include <cuda_runtime.h>

#define KK    9
#define CELLS 81
#define VOL   729
#define NBRD  4
#define BVOL  (VOL * NBRD)   // 2916 floats per block, 16B-aligned
#define NV4   (BVOL / 4)     // 729 float4 per block
#define NT    256

__global__ void __launch_bounds__(NT) sudoku_iterate_kernel(
    const float* __restrict__ s_in,
    const float* __restrict__ rm_in,
    const float* __restrict__ ri_in,
    const float* __restrict__ w_in,
    const float* __restrict__ b_in,
    float* __restrict__ s_out,
    float* __restrict__ rm_out,
    float* __restrict__ ri_out)
{
    __shared__ int   sh_cell0[NBRD];
    __shared__ int   sh_e0[NBRD];
    __shared__ float sh_mval[NBRD];
    __shared__ float sh_cmc[NBRD];
    __shared__ float sh_ri[NBRD];

    const int blk = blockIdx.x;
    const int t   = threadIdx.x;
    const long base = (long)blk * BVOL;

    const float4* s4p = (const float4*)(s_in + base);
    const float4* r4p = (const float4*)(rm_in + base);
    float4* so4 = (float4*)(s_out + base);
    float4* ro4 = (float4*)(rm_out + base);

    // ---- front-load everything ----
    const bool has2 = (t < NV4 - 2 * NT);     // t < 217
    float4 s0 = s4p[t];
    float4 s1 = s4p[t + NT];
    float4 r0 = r4p[t];
    float4 r1 = r4p[t + NT];
    float4 s2 = make_float4(0,0,0,0), r2 = make_float4(0,0,0,0);
    if (has2) { s2 = s4p[t + 2 * NT]; r2 = r4p[t + 2 * NT]; }
    const float cb  = b_in[0];
    const float cme = fminf(fmaxf(cb, 0.0f), 1.0f);
    const bool  fast = (cme == 0.0f);         // bench case: conv_b == 0

    // ---- FAST PATH bulk: outputs independent of the decision -> store NOW,
    //      no barrier on the streaming critical path ----
    if (fast) {
        float4 o;
        o.x = fmaxf(r0.x, 0.0f); o.y = fmaxf(r0.y, 0.0f);
        o.z = fmaxf(r0.z, 0.0f); o.w = fmaxf(r0.w, 0.0f);
        so4[t] = s0;  ro4[t] = o;
        o.x = fmaxf(r1.x, 0.0f); o.y = fmaxf(r1.y, 0.0f);
        o.z = fmaxf(r1.z, 0.0f); o.w = fmaxf(r1.w, 0.0f);
        so4[t + NT] = s1;  ro4[t + NT] = o;
        if (has2) {
            o.x = fmaxf(r2.x, 0.0f); o.y = fmaxf(r2.y, 0.0f);
            o.z = fmaxf(r2.z, 0.0f); o.w = fmaxf(r2.w, 0.0f);
            so4[t + 2 * NT] = s2;  ro4[t + 2 * NT] = o;
        }
    }

    // ---- warps 0..3: decision for boards 0..3 (concurrent with bulk stores) ----
    const int wid = t >> 5, lane = t & 31;
    if (wid < NBRD) {
        const float* sb = s_in + base + wid * VOL;
        float w[KK];
        #pragma unroll
        for (int n = 0; n < KK; n++) w[n] = w_in[n];

        float bv = -3.0e38f; int bi = 0;
        #pragma unroll
        for (int j3 = 0; j3 < 3; j3++) {
            int cell = lane + 32 * j3;
            if (cell < CELLS) {
                float c = cb;
                #pragma unroll
                for (int n = 0; n < KK; n++)
                    c = fmaf(sb[n * CELLS + cell], w[n], c);
                float nic = fmaxf(c - 1.0f, 0.0f);
                float m0  = fminf(fmaxf(1.0f - fabsf(nic), 0.0f), 1.0f) * (-(float)KK);
                float v   = m0 - nic;
                if (v > bv) { bv = v; bi = cell; }     // first-max (ascending cells)
            }
        }
        #pragma unroll
        for (int off = 16; off; off >>= 1) {
            float ov = __shfl_xor_sync(0xffffffffu, bv, off);
            int   oi = __shfl_xor_sync(0xffffffffu, bi, off);
            if (ov > bv || (ov == bv && oi < bi)) { bv = ov; bi = oi; }
        }

        float mv = (lane < KK) ? sb[lane * CELLS + bi] : -3.0e38f;
        int   mi = lane;
        #pragma unroll
        for (int off = 16; off; off >>= 1) {
            float ov = __shfl_xor_sync(0xffffffffu, mv, off);
            int   oi = __shfl_xor_sync(0xffffffffu, mi, off);
            if (ov > mv || (ov == mv && oi < mi)) { mv = ov; mi = oi; }
        }

        if (lane == 0) {
            sh_cell0[wid] = bi;
            sh_e0[wid]    = wid * VOL + mi * CELLS + bi;
            sh_mval[wid]  = mv;
            sh_cmc[wid]   = fminf(fmaxf(fmaf(mv, w[mi], cb), 0.0f), 1.0f);
            sh_ri[wid]    = ri_in[blk * NBRD + wid];
        }
    }
    __syncthreads();   // orders bulk stores before fixup rewrites; publishes decision

    if (fast) {
        // ---- fixup: 9 chosen-cell elements per board (36 threads) ----
        if (t < NBRD * KK) {
            const int   j     = t / KK;          // board
            const int   n     = t - j * KK;      // number channel
            const int   cell0 = sh_cell0[j];
            const int   f     = j * VOL + n * CELLS + cell0;
            const int   e0    = sh_e0[j];
            const float mval  = sh_mval[j];
            const float cmc   = sh_cmc[j];
            const float ri    = sh_ri[j];

            const float s   = s_in[base + f];    // L1/L2-hot
            const float r   = rm_in[base + f];
            const float ov  = (f == e0) ? mval : 0.0f;
            const float orm = s * cmc * (1.0f - ov);
            s_out [base + f] = s * (1.0f - orm);
            rm_out[base + f] = fmaxf(r, fmaxf(ri * orm, (ri - 1.0f) * ov));
        }
    } else {
        // ---- GENERAL PATH (cme != 0): full R3-proven elementwise body ----
        #pragma unroll
        for (int it = 0; it < 3; it++) {
            if (it == 2 && !has2) break;
            const int p = t + it * NT;
            const int e = 4 * p;
            const float4 sv = (it == 0) ? s0 : (it == 1) ? s1 : s2;
            const float4 rv = (it == 0) ? r0 : (it == 1) ? r1 : r2;

            const int j0 = (e >= VOL) + (e >= 2 * VOL) + (e >= 3 * VOL);
            const int j3 = (e + 3 >= VOL) + (e + 3 >= 2 * VOL) + (e + 3 >= 3 * VOL);
            const int c0 = e % CELLS;

            float4 so, ro;
            if (j0 == j3) {
                const int   cell0 = sh_cell0[j0];
                const int   e0    = sh_e0[j0];
                const float mval  = sh_mval[j0];
                const float cmc   = sh_cmc[j0];
                const float ri    = sh_ri[j0];
                #pragma unroll
                for (int k = 0; k < 4; k++) {
                    int cell = c0 + k; if (cell >= CELLS) cell -= CELLS;
                    const float s   = (&sv.x)[k];
                    const float ov  = (e + k == e0)   ? mval : 0.0f;
                    const float cm  = (cell == cell0) ? cmc  : cme;
                    const float orm = s * cm * (1.0f - ov);
                    (&so.x)[k] = s * (1.0f - orm);
                    (&ro.x)[k] = fmaxf((&rv.x)[k], fmaxf(ri * orm, (ri - 1.0f) * ov));
                }
            } else {
                #pragma unroll
                for (int k = 0; k < 4; k++) {
                    const int f = e + k;
                    const int j = (f >= VOL) + (f >= 2 * VOL) + (f >= 3 * VOL);
                    int cell = c0 + k; if (cell >= CELLS) cell -= CELLS;
                    const float s   = (&sv.x)[k];
                    const float ov  = (f == sh_e0[j])       ? sh_mval[j] : 0.0f;
                    const float cm  = (cell == sh_cell0[j]) ? sh_cmc[j]  : cme;
                    const float orm = s * cm * (1.0f - ov);
                    const float ri  = sh_ri[j];
                    (&so.x)[k] = s * (1.0f - orm);
                    (&ro.x)[k] = fmaxf((&rv.x)[k], fmaxf(ri * orm, (ri - 1.0f) * ov));
                }
            }
            so4[p] = so;
            ro4[p] = ro;
        }
    }

    if (t < NBRD) ri_out[blk * NBRD + t] = sh_ri[t] + 1.0f;
}

extern "C" void kernel_launch(void* const* d_in, const int* in_sizes, int n_in,
                              void* d_out, int out_size)
{
    const float* s_in  = (const float*)d_in[0];
    const float* rm_in = (const float*)d_in[1];
    const float* ri_in = (const float*)d_in[2];
    const float* w_in  = (const float*)d_in[3];
    const float* b_in  = (const float*)d_in[4];

    const int B = in_sizes[0] / VOL;

    float* out    = (float*)d_out;
    float* s_out  = out;
    float* rm_out = out + (long)B * VOL;
    float* ri_out = out + 2L * (long)B * VOL;

    sudoku_iterate_kernel<<<B / NBRD, NT>>>(s_in, rm_in, ri_in, w_in, b_in,
                                            s_out, rm_out, ri_out);
}

// round 14
// speedup vs baseline: 1.1468x; 1.1468x over previous
#include <cuda_runtime.h>

#define KK    9
#define CELLS 81
#define VOL   729
#define NBRD  4
#define BVOL  (VOL * NBRD)   // 2916 floats per block, 16B-aligned
#define NV4   (BVOL / 4)     // 729 float4 per block
#define NT    128            // 4 warps: every warp decides one board
#define NIT   6              // 5 full iterations + 1 partial (t < 89)

__global__ void __launch_bounds__(NT) sudoku_iterate_kernel(
    const float* __restrict__ s_in,
    const float* __restrict__ rm_in,
    const float* __restrict__ ri_in,
    const float* __restrict__ w_in,
    const float* __restrict__ b_in,
    float* __restrict__ s_out,
    float* __restrict__ rm_out,
    float* __restrict__ ri_out)
{
    __shared__ int   sh_cell0[NBRD];
    __shared__ int   sh_e0[NBRD];
    __shared__ float sh_mval[NBRD];
    __shared__ float sh_cmc[NBRD];
    __shared__ float sh_ri[NBRD];

    const int blk = blockIdx.x;
    const int t   = threadIdx.x;
    const long base = (long)blk * BVOL;

    const float4* s4p = (const float4*)(s_in + base);
    const float4* r4p = (const float4*)(rm_in + base);

    // ---- front-load ALL elementwise data: 12 LDG.128 in flight per thread ----
    const bool has5 = (t < NV4 - 5 * NT);     // t < 89
    float4 sA[NIT], rA[NIT];
    #pragma unroll
    for (int i = 0; i < 5; i++) { sA[i] = s4p[t + i * NT]; rA[i] = r4p[t + i * NT]; }
    sA[5] = make_float4(0,0,0,0); rA[5] = make_float4(0,0,0,0);
    if (has5) { sA[5] = s4p[t + 5 * NT]; rA[5] = r4p[t + 5 * NT]; }
    const float cb = b_in[0];

    // ---- ALL 4 warps decide: warp w handles board w (NT=128 -> wid in 0..3) ----
    const int wid = t >> 5, lane = t & 31;
    {
        const float* sb = s_in + base + wid * VOL;
        float w[KK];
        #pragma unroll
        for (int n = 0; n < KK; n++) w[n] = w_in[n];

        float bv = -3.0e38f; int bi = 0;
        #pragma unroll
        for (int j3 = 0; j3 < 3; j3++) {
            int cell = lane + 32 * j3;
            if (cell < CELLS) {
                float c = cb;
                #pragma unroll
                for (int n = 0; n < KK; n++)
                    c = fmaf(sb[n * CELLS + cell], w[n], c);
                float nic = fmaxf(c - 1.0f, 0.0f);
                float m0  = fminf(fmaxf(1.0f - fabsf(nic), 0.0f), 1.0f) * (-(float)KK);
                float v   = m0 - nic;
                if (v > bv) { bv = v; bi = cell; }     // first-max (ascending cells)
            }
        }
        #pragma unroll
        for (int off = 16; off; off >>= 1) {
            float ov = __shfl_xor_sync(0xffffffffu, bv, off);
            int   oi = __shfl_xor_sync(0xffffffffu, bi, off);
            if (ov > bv || (ov == bv && oi < bi)) { bv = ov; bi = oi; }
        }

        float mv = (lane < KK) ? sb[lane * CELLS + bi] : -3.0e38f;
        int   mi = lane;
        #pragma unroll
        for (int off = 16; off; off >>= 1) {
            float ov = __shfl_xor_sync(0xffffffffu, mv, off);
            int   oi = __shfl_xor_sync(0xffffffffu, mi, off);
            if (ov > mv || (ov == mv && oi < mi)) { mv = ov; mi = oi; }
        }

        if (lane == 0) {
            sh_cell0[wid] = bi;
            sh_e0[wid]    = wid * VOL + mi * CELLS + bi;
            sh_mval[wid]  = mv;
            sh_cmc[wid]   = fminf(fmaxf(fmaf(mv, w[mi], cb), 0.0f), 1.0f);
            sh_ri[wid]    = ri_in[blk * NBRD + wid];
        }
    }
    __syncthreads();   // the ONLY barrier

    const float cme = fminf(fmaxf(cb, 0.0f), 1.0f);
    float4* so4 = (float4*)(s_out + base);
    float4* ro4 = (float4*)(rm_out + base);

    #pragma unroll
    for (int it = 0; it < NIT; it++) {
        if (it == 5 && !has5) break;
        const int p = t + it * NT;
        const int e = 4 * p;
        const float4 sv = sA[it];
        const float4 rv = rA[it];

        const int j0 = (e >= VOL) + (e >= 2 * VOL) + (e >= 3 * VOL);
        const int j3 = (e + 3 >= VOL) + (e + 3 >= 2 * VOL) + (e + 3 >= 3 * VOL);
        const int c0 = e % CELLS;             // 729 % 81 == 0 -> board-independent

        float4 so, ro;
        if (j0 == j3) {                       // whole float4 inside one board
            const int   cell0 = sh_cell0[j0];
            const int   e0    = sh_e0[j0];
            const float mval  = sh_mval[j0];
            const float cmc   = sh_cmc[j0];
            const float ri    = sh_ri[j0];
            #pragma unroll
            for (int k = 0; k < 4; k++) {
                int cell = c0 + k; if (cell >= CELLS) cell -= CELLS;
                const float s   = (&sv.x)[k];
                const float ov  = (e + k == e0)   ? mval : 0.0f;
                const float cm  = (cell == cell0) ? cmc  : cme;
                const float orm = s * cm * (1.0f - ov);
                (&so.x)[k] = s * (1.0f - orm);
                (&ro.x)[k] = fmaxf((&rv.x)[k], fmaxf(ri * orm, (ri - 1.0f) * ov));
            }
        } else {                              // straddles a board boundary (rare)
            #pragma unroll
            for (int k = 0; k < 4; k++) {
                const int f = e + k;
                const int j = (f >= VOL) + (f >= 2 * VOL) + (f >= 3 * VOL);
                int cell = c0 + k; if (cell >= CELLS) cell -= CELLS;
                const float s   = (&sv.x)[k];
                const float ov  = (f == sh_e0[j])       ? sh_mval[j] : 0.0f;
                const float cm  = (cell == sh_cell0[j]) ? sh_cmc[j]  : cme;
                const float orm = s * cm * (1.0f - ov);
                const float ri  = sh_ri[j];
                (&so.x)[k] = s * (1.0f - orm);
                (&ro.x)[k] = fmaxf((&rv.x)[k], fmaxf(ri * orm, (ri - 1.0f) * ov));
            }
        }
        so4[p] = so;
        ro4[p] = ro;
    }

    if (t < NBRD) ri_out[blk * NBRD + t] = sh_ri[t] + 1.0f;
}

extern "C" void kernel_launch(void* const* d_in, const int* in_sizes, int n_in,
                              void* d_out, int out_size)
{
    const float* s_in  = (const float*)d_in[0];
    const float* rm_in = (const float*)d_in[1];
    const float* ri_in = (const float*)d_in[2];
    const float* w_in  = (const float*)d_in[3];
    const float* b_in  = (const float*)d_in[4];

    const int B = in_sizes[0] / VOL;

    float* out    = (float*)d_out;
    float* s_out  = out;
    float* rm_out = out + (long)B * VOL;
    float* ri_out = out + 2L * (long)B * VOL;

    sudoku_iterate_kernel<<<B / NBRD, NT>>>(s_in, rm_in, ri_in, w_in, b_in,
                                            s_out, rm_out, ri_out);
}